// round 11
// baseline (speedup 1.0000x reference)
#include <cuda_runtime.h>
#include <math.h>
#include <stdint.h>

#define S_LEN 512
#define BATCH 64
#define IN_SZ 256
#define HID   1024
#define NCTA  128
#define CPC   8            // columns per CTA = HID/NCTA
#define TPB2  256          // recurrence threads: 8 warps

// packed f32x2 FMA is Blackwell-family; guard like tcgen05 so the non-'a'
// compilation pass still builds (fallback = proven scalar loop, same numerics)
#if (defined(__CUDA_ARCH_FEAT_SM103_ALL) || \
     (defined(__CUDA_ARCH_SPECIFIC__) && (__CUDA_ARCH_SPECIFIC__ == 1030)))
#define HAS_F32X2 1
#else
#define HAS_F32X2 0
#endif

// ---------------- scratch / barrier state (no allocs allowed) ----------------
__device__ float    g_xv[(size_t)S_LEN * BATCH * HID];   // x@V + b + b2
__device__ unsigned g_count = 0;   // barrier arrivals (monotone across replays)
__device__ unsigned g_phase = 0;   // barrier generation (monotone across replays)

// ---------------- split software grid barrier (128 co-resident CTAs) ---------
__device__ __forceinline__ void grid_arrive() {
    unsigned ticket;
    asm volatile("atom.add.acq_rel.gpu.u32 %0, [%1], 1;"
                 : "=r"(ticket) : "l"(&g_count) : "memory");
    if ((ticket & (NCTA - 1)) == (NCTA - 1)) {
        asm volatile("red.add.release.gpu.u32 [%0], 1;"
                     :: "l"(&g_phase) : "memory");
    }
}
__device__ __forceinline__ void grid_wait(unsigned target) {
    unsigned p;
    do {
        asm volatile("ld.acquire.gpu.u32 %0, [%1];"
                     : "=r"(p) : "l"(&g_phase) : "memory");
    } while ((int)(p - target) < 0);
}

#if HAS_F32X2
__device__ __forceinline__ unsigned long long pack2(float lo, float hi) {
    unsigned long long d;
    asm("mov.b64 %0, {%1, %2};" : "=l"(d) : "f"(lo), "f"(hi));
    return d;
}
__device__ __forceinline__ unsigned long long ffma2(unsigned long long a,
                                                    unsigned long long b,
                                                    unsigned long long c) {
    unsigned long long d;
    asm("fma.rn.f32x2 %0, %1, %2, %3;" : "=l"(d) : "l"(a), "l"(b), "l"(c));
    return d;
}
#endif

// =============================================================================
// Phase 1: xv[m][n] = X[m][:] @ V[:][n] + b[n] + b2[n],  M=32768, N=1024, K=256
// (unchanged from R4 — proven)
// =============================================================================
__global__ __launch_bounds__(256)
void xv_gemm(const float* __restrict__ X, const float* __restrict__ V,
             const float* __restrict__ b1, const float* __restrict__ b2) {
    __shared__ float As[16][132];
    __shared__ float Bs[16][132];

    const int tid = threadIdx.x;
    const int m0  = blockIdx.y * 128;
    const int n0  = blockIdx.x * 128;
    const int ty  = tid >> 4;
    const int tx  = tid & 15;

    float acc[8][8];
    #pragma unroll
    for (int i = 0; i < 8; i++)
        #pragma unroll
        for (int j = 0; j < 8; j++) acc[i][j] = 0.f;

    for (int k0 = 0; k0 < IN_SZ; k0 += 16) {
        #pragma unroll
        for (int i = 0; i < 2; i++) {
            int lin = i * 256 + tid;
            int row = lin >> 2, q = lin & 3;
            float4 v = *(const float4*)(X + (size_t)(m0 + row) * IN_SZ + k0 + q * 4);
            As[q * 4 + 0][row] = v.x;
            As[q * 4 + 1][row] = v.y;
            As[q * 4 + 2][row] = v.z;
            As[q * 4 + 3][row] = v.w;
        }
        #pragma unroll
        for (int i = 0; i < 2; i++) {
            int lin  = i * 256 + tid;
            int krow = lin >> 5, c4 = lin & 31;
            *(float4*)&Bs[krow][c4 * 4] =
                *(const float4*)(V + (size_t)(k0 + krow) * HID + n0 + c4 * 4);
        }
        __syncthreads();
        #pragma unroll
        for (int k = 0; k < 16; k++) {
            float a[8], bb[8];
            *(float4*)&a[0]  = *(float4*)&As[k][ty * 8];
            *(float4*)&a[4]  = *(float4*)&As[k][ty * 8 + 4];
            *(float4*)&bb[0] = *(float4*)&Bs[k][tx * 8];
            *(float4*)&bb[4] = *(float4*)&Bs[k][tx * 8 + 4];
            #pragma unroll
            for (int i = 0; i < 8; i++)
                #pragma unroll
                for (int j = 0; j < 8; j++)
                    acc[i][j] = fmaf(a[i], bb[j], acc[i][j]);
        }
        __syncthreads();
    }

    float bsum[8];
    #pragma unroll
    for (int j = 0; j < 8; j++)
        bsum[j] = b1[n0 + tx * 8 + j] + b2[n0 + tx * 8 + j];

    #pragma unroll
    for (int i = 0; i < 8; i++) {
        float* dst = g_xv + (size_t)(m0 + ty * 8 + i) * HID + n0 + tx * 8;
        float4 v0 = make_float4(acc[i][0] + bsum[0], acc[i][1] + bsum[1],
                                acc[i][2] + bsum[2], acc[i][3] + bsum[3]);
        float4 v1 = make_float4(acc[i][4] + bsum[4], acc[i][5] + bsum[5],
                                acc[i][6] + bsum[6], acc[i][7] + bsum[7]);
        *(float4*)dst       = v0;
        *(float4*)(dst + 4) = v1;
    }
}

// =============================================================================
// Phase 2: persistent recurrence — R4 architecture + packed f32x2 mainloop.
//   128 CTAs x 256 threads. CTA owns 8 columns of W (smem, k-major).
//   Thread = (warp b-tile: 8 batch rows) x (8 cols as 4 f32x2 pairs)
//            x (lane ks: k-split 32).
//   Per j (8 outer k-blocks of 128): 8 LDS.128 (W, conflict-free) +
//   8 LDG.128.cg (h from L2) + 128 FFMA2 (was 256 FFMA).
//   k-split reduced via padded smem transpose (stride 516, conflict-free).
// =============================================================================
__global__ __launch_bounds__(TPB2, 1)
void rnn_persistent(const float* __restrict__ W, float* out) {
    extern __shared__ float sm[];
    float* Ws = sm;                  // [8][1024]  column-major slices, k contiguous
    float* Ps = sm + 8 * 1024;       // partials: [32 ks][512 outputs + 4 pad]
    const int PSTR = 516;

    const int tid   = threadIdx.x;
    const int cbase = blockIdx.x * CPC;
    const int ks    = tid & 31;      // lane = k-split index
    const int btile = tid >> 5;      // warp id 0..7 -> batch rows btile*8..+7

    // Load W slice: Ws[c*1024 + k] = W[k*HID + cbase + c]
    for (int i = tid; i < 8 * 1024; i += TPB2) {
        int c = i >> 10, k = i & 1023;
        Ws[i] = W[(size_t)k * HID + cbase + c];
    }

    __shared__ unsigned s_base;
    if (tid == 0) {
        unsigned p;
        asm volatile("ld.acquire.gpu.u32 %0, [%1];" : "=r"(p) : "l"(&g_phase) : "memory");
        s_base = p;
    }
    __syncthreads();
    const unsigned base = s_base;

    // Each thread finalizes outputs o0 = 2*tid and o0+1 (o = b*8 + c)
    const int o0 = 2 * tid;
    const int ob = o0 >> 3, oc = o0 & 7;
    const size_t xv_off = (size_t)ob * HID + cbase + oc;
    float2 xv = *(const float2*)(g_xv + xv_off);

    const float* wbase = Ws + ks * 4;
    const size_t hrow0 = (size_t)btile * 8 * HID + (size_t)ks * 4;

    for (int t = 0; t < S_LEN; t++) {
#if HAS_F32X2
        unsigned long long acc2[8][4];
        #pragma unroll
        for (int b = 0; b < 8; b++)
            #pragma unroll
            for (int p = 0; p < 4; p++) acc2[b][p] = 0ULL;

        if (t > 0) {
            const float* prev = out + (size_t)(t - 1) * BATCH * HID + hrow0;
            #pragma unroll 1
            for (int j = 0; j < 8; j++) {
                const int off = j * 128;
                float4 w4[8];
                #pragma unroll
                for (int c = 0; c < 8; c++)
                    w4[c] = *(const float4*)(wbase + c * 1024 + off);
                float4 h4[8];
                #pragma unroll
                for (int b = 0; b < 8; b++)
                    h4[b] = __ldcg((const float4*)(prev + (size_t)b * HID + off));
                #pragma unroll
                for (int kk = 0; kk < 4; kk++) {
                    unsigned long long w2[4];
                    #pragma unroll
                    for (int p = 0; p < 4; p++)
                        w2[p] = pack2(((const float*)&w4[2 * p])[kk],
                                      ((const float*)&w4[2 * p + 1])[kk]);
                    #pragma unroll
                    for (int b = 0; b < 8; b++) {
                        float hk = ((const float*)&h4[b])[kk];
                        unsigned long long hd = pack2(hk, hk);
                        #pragma unroll
                        for (int p = 0; p < 4; p++)
                            acc2[b][p] = ffma2(hd, w2[p], acc2[b][p]);
                    }
                }
            }
        }

        // ---- k-split reduction via smem transpose (layout identical to R4) ----
        float* prow = Ps + ks * PSTR + btile * 64;   // outputs (btile*8+b)*8+c
        #pragma unroll
        for (int b = 0; b < 8; b++) {
            #pragma unroll
            for (int p = 0; p < 4; p++)
                *(unsigned long long*)(prow + b * 8 + 2 * p) = acc2[b][p];
        }
#else
        float acc[8][8];
        #pragma unroll
        for (int b = 0; b < 8; b++)
            #pragma unroll
            for (int c = 0; c < 8; c++) acc[b][c] = 0.f;

        if (t > 0) {
            const float* prev = out + (size_t)(t - 1) * BATCH * HID + hrow0;
            #pragma unroll 1
            for (int j = 0; j < 8; j++) {
                const int off = j * 128;
                float4 w[8];
                #pragma unroll
                for (int c = 0; c < 8; c++)
                    w[c] = *(const float4*)(wbase + c * 1024 + off);
                float4 h[8];
                #pragma unroll
                for (int b = 0; b < 8; b++)
                    h[b] = __ldcg((const float4*)(prev + (size_t)b * HID + off));
                #pragma unroll
                for (int b = 0; b < 8; b++) {
                    #pragma unroll
                    for (int c = 0; c < 8; c++) {
                        acc[b][c] = fmaf(h[b].x, w[c].x, acc[b][c]);
                        acc[b][c] = fmaf(h[b].y, w[c].y, acc[b][c]);
                        acc[b][c] = fmaf(h[b].z, w[c].z, acc[b][c]);
                        acc[b][c] = fmaf(h[b].w, w[c].w, acc[b][c]);
                    }
                }
            }
        }

        float* prow = Ps + ks * PSTR + btile * 64;
        #pragma unroll
        for (int b = 0; b < 8; b++) {
            *(float4*)(prow + b * 8)     = make_float4(acc[b][0], acc[b][1],
                                                       acc[b][2], acc[b][3]);
            *(float4*)(prow + b * 8 + 4) = make_float4(acc[b][4], acc[b][5],
                                                       acc[b][6], acc[b][7]);
        }
#endif
        __syncthreads();

        float sx = 0.f, sy = 0.f;
        #pragma unroll
        for (int p = 0; p < 32; p++) {
            float2 v = *(const float2*)(Ps + p * PSTR + o0);
            sx += v.x; sy += v.y;
        }
        float r0 = tanhf(sx + xv.x);
        float r1 = tanhf(sy + xv.y);

        float* dst = out + (size_t)t * BATCH * HID + xv_off;
        *(float2*)dst = make_float2(r0, r1);
        if (t == S_LEN - 1)
            *(float2*)(out + (size_t)S_LEN * BATCH * HID + xv_off) = make_float2(r0, r1);

        // ---- split grid barrier: arrive, prefetch next xv, wait ----
        __syncthreads();                  // stores issued + Ps reads done
        if (tid == 0) grid_arrive();
        if (t + 1 < S_LEN)
            xv = *(const float2*)(g_xv + (size_t)(t + 1) * BATCH * HID + xv_off);
        if (tid == 0) grid_wait(base + (unsigned)t + 1u);
        __syncthreads();
    }
}

// =============================================================================
// launch
// =============================================================================
extern "C" void kernel_launch(void* const* d_in, const int* in_sizes, int n_in,
                              void* d_out, int out_size) {
    const float* x  = (const float*)d_in[0];
    const float* V  = (const float*)d_in[1];
    const float* W  = (const float*)d_in[2];
    const float* b  = (const float*)d_in[3];
    const float* b2 = (const float*)d_in[4];
    float* out = (float*)d_out;

    dim3 g1(HID / 128, (S_LEN * BATCH) / 128);
    xv_gemm<<<g1, 256>>>(x, V, b, b2);

    const int smem_bytes = (8 * 1024 + 32 * 516) * (int)sizeof(float); // 98816
    cudaFuncSetAttribute(rnn_persistent,
                         cudaFuncAttributeMaxDynamicSharedMemorySize, smem_bytes);
    rnn_persistent<<<NCTA, TPB2, smem_bytes>>>(W, out);
}

// round 12
// speedup vs baseline: 1.3170x; 1.3170x over previous
#include <cuda_runtime.h>
#include <math.h>
#include <stdint.h>

#define S_LEN 512
#define BATCH 64
#define IN_SZ 256
#define HID   1024
#define NCTA  128
#define CPC   8            // columns per CTA = HID/NCTA
#define TPB2  512          // recurrence threads: 16 warps
#define BH    (BATCH * HID)

// ---------------- scratch / barrier state (no allocs allowed) ----------------
__device__ float    g_xv[(size_t)S_LEN * BATCH * HID];   // x@V + b + b2
__device__ unsigned g_count = 0;   // barrier arrivals (monotone across replays)
__device__ unsigned g_phase = 0;   // barrier generation (monotone across replays)

// ---------------- split software grid barrier (128 co-resident CTAs) ---------
__device__ __forceinline__ void grid_arrive() {
    unsigned ticket;
    asm volatile("atom.add.acq_rel.gpu.u32 %0, [%1], 1;"
                 : "=r"(ticket) : "l"(&g_count) : "memory");
    if ((ticket & (NCTA - 1)) == (NCTA - 1)) {
        asm volatile("red.add.release.gpu.u32 [%0], 1;"
                     :: "l"(&g_phase) : "memory");
    }
}
__device__ __forceinline__ void grid_wait(unsigned target) {
    unsigned p;
    do {
        asm volatile("ld.acquire.gpu.u32 %0, [%1];"
                     : "=r"(p) : "l"(&g_phase) : "memory");
    } while ((int)(p - target) < 0);
}

// =============================================================================
// Phase 1: xv[m][n] = X[m][:] @ V[:][n] + b[n] + b2[n],  M=32768, N=1024, K=256
// (unchanged — proven)
// =============================================================================
__global__ __launch_bounds__(256)
void xv_gemm(const float* __restrict__ X, const float* __restrict__ V,
             const float* __restrict__ b1, const float* __restrict__ b2) {
    __shared__ float As[16][132];
    __shared__ float Bs[16][132];

    const int tid = threadIdx.x;
    const int m0  = blockIdx.y * 128;
    const int n0  = blockIdx.x * 128;
    const int ty  = tid >> 4;
    const int tx  = tid & 15;

    float acc[8][8];
    #pragma unroll
    for (int i = 0; i < 8; i++)
        #pragma unroll
        for (int j = 0; j < 8; j++) acc[i][j] = 0.f;

    for (int k0 = 0; k0 < IN_SZ; k0 += 16) {
        #pragma unroll
        for (int i = 0; i < 2; i++) {
            int lin = i * 256 + tid;
            int row = lin >> 2, q = lin & 3;
            float4 v = *(const float4*)(X + (size_t)(m0 + row) * IN_SZ + k0 + q * 4);
            As[q * 4 + 0][row] = v.x;
            As[q * 4 + 1][row] = v.y;
            As[q * 4 + 2][row] = v.z;
            As[q * 4 + 3][row] = v.w;
        }
        #pragma unroll
        for (int i = 0; i < 2; i++) {
            int lin  = i * 256 + tid;
            int krow = lin >> 5, c4 = lin & 31;
            *(float4*)&Bs[krow][c4 * 4] =
                *(const float4*)(V + (size_t)(k0 + krow) * HID + n0 + c4 * 4);
        }
        __syncthreads();
        #pragma unroll
        for (int k = 0; k < 16; k++) {
            float a[8], bb[8];
            *(float4*)&a[0]  = *(float4*)&As[k][ty * 8];
            *(float4*)&a[4]  = *(float4*)&As[k][ty * 8 + 4];
            *(float4*)&bb[0] = *(float4*)&Bs[k][tx * 8];
            *(float4*)&bb[4] = *(float4*)&Bs[k][tx * 8 + 4];
            #pragma unroll
            for (int i = 0; i < 8; i++)
                #pragma unroll
                for (int j = 0; j < 8; j++)
                    acc[i][j] = fmaf(a[i], bb[j], acc[i][j]);
        }
        __syncthreads();
    }

    float bsum[8];
    #pragma unroll
    for (int j = 0; j < 8; j++)
        bsum[j] = b1[n0 + tx * 8 + j] + b2[n0 + tx * 8 + j];

    #pragma unroll
    for (int i = 0; i < 8; i++) {
        float* dst = g_xv + (size_t)(m0 + ty * 8 + i) * HID + n0 + tx * 8;
        float4 v0 = make_float4(acc[i][0] + bsum[0], acc[i][1] + bsum[1],
                                acc[i][2] + bsum[2], acc[i][3] + bsum[3]);
        float4 v1 = make_float4(acc[i][4] + bsum[4], acc[i][5] + bsum[5],
                                acc[i][6] + bsum[6], acc[i][7] + bsum[7]);
        *(float4*)dst       = v0;
        *(float4*)(dst + 4) = v1;
    }
}

// =============================================================================
// Phase 2: persistent recurrence — R4 architecture, 16 warps + h prefetch.
//   128 CTAs x 512 threads (occ 25%). CTA owns 8 columns of W (smem, k-major).
//   Thread = (warp: 4 batch rows) x (all 8 cols) x (lane ks: k-split 32).
//   Per j (8 outer k-blocks of 128): 8 LDS.128 (W) + 4 LDG.128.cg (h from L2,
//   prefetched one block ahead) + 128 FFMA. 32 fp32 accumulators per thread.
//   h L2 traffic identical to R4 (each element read once per CTA).
//   k-split reduced via padded smem transpose; 1 output per thread.
// =============================================================================
__global__ __launch_bounds__(TPB2, 1)
void rnn_persistent(const float* __restrict__ W, float* out) {
    extern __shared__ float sm[];
    float* Ws = sm;                  // [8][1024]  column-major slices, k contiguous
    float* Ps = sm + 8 * 1024;       // partials: [32 ks][512 outputs + 4 pad]
    const int PSTR = 516;

    const int tid   = threadIdx.x;
    const int cbase = blockIdx.x * CPC;
    const int ks    = tid & 31;      // lane = k-split index
    const int wtile = tid >> 5;      // warp id 0..15 -> batch rows wtile*4..+3

    // Load W slice: Ws[c*1024 + k] = W[k*HID + cbase + c]
    for (int i = tid; i < 8 * 1024; i += TPB2) {
        int c = i >> 10, k = i & 1023;
        Ws[i] = W[(size_t)k * HID + cbase + c];
    }

    __shared__ unsigned s_base;
    if (tid == 0) {
        unsigned p;
        asm volatile("ld.acquire.gpu.u32 %0, [%1];" : "=r"(p) : "l"(&g_phase) : "memory");
        s_base = p;
    }
    __syncthreads();
    const unsigned base = s_base;

    // Each thread finalizes ONE output o = tid  (o = b*8 + c)
    const int ob = tid >> 3, oc = tid & 7;
    const size_t xv_off = (size_t)ob * HID + cbase + oc;
    float xv = g_xv[xv_off];

    const float* wbase = Ws + ks * 4;
    const size_t hrow0 = (size_t)wtile * 4 * HID + (size_t)ks * 4;

    for (int t = 0; t < S_LEN; t++) {
        float acc[4][8];
        #pragma unroll
        for (int b = 0; b < 4; b++)
            #pragma unroll
            for (int c = 0; c < 8; c++) acc[b][c] = 0.f;

        if (t > 0) {
            const float* prev = out + (size_t)(t - 1) * BH + hrow0;

            // prologue: h for k-block 0
            float4 h4[4];
            #pragma unroll
            for (int b = 0; b < 4; b++)
                h4[b] = __ldcg((const float4*)(prev + (size_t)b * HID));

            #pragma unroll 1
            for (int j = 0; j < 8; j++) {
                const int off = j * 128;

                // prefetch next k-block's h while this block computes
                float4 hn[4];
                if (j < 7) {
                    #pragma unroll
                    for (int b = 0; b < 4; b++)
                        hn[b] = __ldcg((const float4*)(prev + (size_t)b * HID + off + 128));
                }

                float4 w4[8];
                #pragma unroll
                for (int c = 0; c < 8; c++)
                    w4[c] = *(const float4*)(wbase + c * 1024 + off);

                #pragma unroll
                for (int b = 0; b < 4; b++) {
                    #pragma unroll
                    for (int c = 0; c < 8; c++) {
                        acc[b][c] = fmaf(h4[b].x, w4[c].x, acc[b][c]);
                        acc[b][c] = fmaf(h4[b].y, w4[c].y, acc[b][c]);
                        acc[b][c] = fmaf(h4[b].z, w4[c].z, acc[b][c]);
                        acc[b][c] = fmaf(h4[b].w, w4[c].w, acc[b][c]);
                    }
                }

                if (j < 7) {
                    #pragma unroll
                    for (int b = 0; b < 4; b++) h4[b] = hn[b];
                }
            }
        }

        // ---- k-split reduction via smem transpose ----
        float* prow = Ps + ks * PSTR + wtile * 32;   // outputs (wtile*4+b)*8+c
        #pragma unroll
        for (int b = 0; b < 4; b++) {
            *(float4*)(prow + b * 8)     = make_float4(acc[b][0], acc[b][1],
                                                       acc[b][2], acc[b][3]);
            *(float4*)(prow + b * 8 + 4) = make_float4(acc[b][4], acc[b][5],
                                                       acc[b][6], acc[b][7]);
        }
        __syncthreads();

        float s = 0.f;
        #pragma unroll
        for (int p = 0; p < 32; p++)
            s += Ps[p * PSTR + tid];
        float r = tanhf(s + xv);

        out[(size_t)t * BH + xv_off] = r;
        if (t == S_LEN - 1)
            out[(size_t)S_LEN * BH + xv_off] = r;

        // ---- split grid barrier: arrive, prefetch next xv, wait ----
        __syncthreads();                  // stores issued + Ps reads done
        if (tid == 0) grid_arrive();
        if (t + 1 < S_LEN)
            xv = g_xv[(size_t)(t + 1) * BH + xv_off];
        if (tid == 0) grid_wait(base + (unsigned)t + 1u);
        __syncthreads();
    }
}

// =============================================================================
// launch
// =============================================================================
extern "C" void kernel_launch(void* const* d_in, const int* in_sizes, int n_in,
                              void* d_out, int out_size) {
    const float* x  = (const float*)d_in[0];
    const float* V  = (const float*)d_in[1];
    const float* W  = (const float*)d_in[2];
    const float* b  = (const float*)d_in[3];
    const float* b2 = (const float*)d_in[4];
    float* out = (float*)d_out;

    dim3 g1(HID / 128, (S_LEN * BATCH) / 128);
    xv_gemm<<<g1, 256>>>(x, V, b, b2);

    const int smem_bytes = (8 * 1024 + 32 * 516) * (int)sizeof(float); // 98816
    cudaFuncSetAttribute(rnn_persistent,
                         cudaFuncAttributeMaxDynamicSharedMemorySize, smem_bytes);
    rnn_persistent<<<NCTA, TPB2, smem_bytes>>>(W, out);
}

// round 13
// speedup vs baseline: 1.4002x; 1.0631x over previous
#include <cuda_runtime.h>
#include <math.h>
#include <stdint.h>

#define S_LEN 512
#define BATCH 64
#define IN_SZ 256
#define HID   1024
#define NCTA  128
#define CPC   8            // columns per CTA = HID/NCTA
#define TPB2  512          // recurrence threads: 16 warps
#define BH    (BATCH * HID)

typedef unsigned long long ull;

// packed f32x2 FMA exists only in the arch-specific ('a') compilation pass
#if (defined(__CUDA_ARCH_FEAT_SM103_ALL) || \
     (defined(__CUDA_ARCH_SPECIFIC__) && (__CUDA_ARCH_SPECIFIC__ == 1030)))
#define HAS_F32X2 1
#else
#define HAS_F32X2 0
#endif

// ---------------- scratch / barrier state (no allocs allowed) ----------------
__device__ float    g_xv[(size_t)S_LEN * BATCH * HID];   // x@V + b + b2
__device__ unsigned g_count = 0;   // barrier arrivals (monotone across replays)
__device__ unsigned g_phase = 0;   // barrier generation (monotone across replays)

// ---------------- split software grid barrier (128 co-resident CTAs) ---------
__device__ __forceinline__ void grid_arrive() {
    unsigned ticket;
    asm volatile("atom.add.acq_rel.gpu.u32 %0, [%1], 1;"
                 : "=r"(ticket) : "l"(&g_count) : "memory");
    if ((ticket & (NCTA - 1)) == (NCTA - 1)) {
        asm volatile("red.add.release.gpu.u32 [%0], 1;"
                     :: "l"(&g_phase) : "memory");
    }
}
__device__ __forceinline__ void grid_wait(unsigned target) {
    unsigned p;
    do {
        asm volatile("ld.acquire.gpu.u32 %0, [%1];"
                     : "=r"(p) : "l"(&g_phase) : "memory");
    } while ((int)(p - target) < 0);
}

#if HAS_F32X2
__device__ __forceinline__ ull pack2(float lo, float hi) {
    ull d;
    asm("mov.b64 %0, {%1, %2};" : "=l"(d) : "f"(lo), "f"(hi));
    return d;
}
__device__ __forceinline__ ull ffma2(ull a, ull b, ull c) {
    ull d;
    asm("fma.rn.f32x2 %0, %1, %2, %3;" : "=l"(d) : "l"(a), "l"(b), "l"(c));
    return d;
}
#endif

// =============================================================================
// Phase 1: xv[m][n] = X[m][:] @ V[:][n] + b[n] + b2[n]  (unchanged — proven)
// =============================================================================
__global__ __launch_bounds__(256)
void xv_gemm(const float* __restrict__ X, const float* __restrict__ V,
             const float* __restrict__ b1, const float* __restrict__ b2) {
    __shared__ float As[16][132];
    __shared__ float Bs[16][132];

    const int tid = threadIdx.x;
    const int m0  = blockIdx.y * 128;
    const int n0  = blockIdx.x * 128;
    const int ty  = tid >> 4;
    const int tx  = tid & 15;

    float acc[8][8];
    #pragma unroll
    for (int i = 0; i < 8; i++)
        #pragma unroll
        for (int j = 0; j < 8; j++) acc[i][j] = 0.f;

    for (int k0 = 0; k0 < IN_SZ; k0 += 16) {
        #pragma unroll
        for (int i = 0; i < 2; i++) {
            int lin = i * 256 + tid;
            int row = lin >> 2, q = lin & 3;
            float4 v = *(const float4*)(X + (size_t)(m0 + row) * IN_SZ + k0 + q * 4);
            As[q * 4 + 0][row] = v.x;
            As[q * 4 + 1][row] = v.y;
            As[q * 4 + 2][row] = v.z;
            As[q * 4 + 3][row] = v.w;
        }
        #pragma unroll
        for (int i = 0; i < 2; i++) {
            int lin  = i * 256 + tid;
            int krow = lin >> 5, c4 = lin & 31;
            *(float4*)&Bs[krow][c4 * 4] =
                *(const float4*)(V + (size_t)(k0 + krow) * HID + n0 + c4 * 4);
        }
        __syncthreads();
        #pragma unroll
        for (int k = 0; k < 16; k++) {
            float a[8], bb[8];
            *(float4*)&a[0]  = *(float4*)&As[k][ty * 8];
            *(float4*)&a[4]  = *(float4*)&As[k][ty * 8 + 4];
            *(float4*)&bb[0] = *(float4*)&Bs[k][tx * 8];
            *(float4*)&bb[4] = *(float4*)&Bs[k][tx * 8 + 4];
            #pragma unroll
            for (int i = 0; i < 8; i++)
                #pragma unroll
                for (int j = 0; j < 8; j++)
                    acc[i][j] = fmaf(a[i], bb[j], acc[i][j]);
        }
        __syncthreads();
    }

    float bsum[8];
    #pragma unroll
    for (int j = 0; j < 8; j++)
        bsum[j] = b1[n0 + tx * 8 + j] + b2[n0 + tx * 8 + j];

    #pragma unroll
    for (int i = 0; i < 8; i++) {
        float* dst = g_xv + (size_t)(m0 + ty * 8 + i) * HID + n0 + tx * 8;
        float4 v0 = make_float4(acc[i][0] + bsum[0], acc[i][1] + bsum[1],
                                acc[i][2] + bsum[2], acc[i][3] + bsum[3]);
        float4 v1 = make_float4(acc[i][4] + bsum[4], acc[i][5] + bsum[5],
                                acc[i][6] + bsum[6], acc[i][7] + bsum[7]);
        *(float4*)dst       = v0;
        *(float4*)(dst + 4) = v1;
    }
}

// =============================================================================
// Phase 2: persistent recurrence — R12 architecture + pre-paired-W FFMA2.
//   128 CTAs x 512 threads (occ 25%). CTA owns 8 columns of W, stored in smem
//   as f32x2 column-pairs in a lane-interleaved layout: the 16B element for
//   (j-block, i=pair*2+khalf, lane ks) sits at uint4 index (j*8+i)*32+ks, so
//   each warp's per-j fetch is 8 dense conflict-free LDS.128 yielding
//   ready-made b64 W operands (zero runtime w-packing).
//   Thread = (warp: 4 batch rows) x (8 cols as 4 f32x2 pairs) x (lane ks).
//   Per j: 8 LDS.128 (W pairs) + 4 LDG.128.cg (h, prefetched) + 16 mov.b64
//   (h dup) + 64 FFMA2 (=128 FMA). Accumulator memory image identical to R12.
// =============================================================================
__global__ __launch_bounds__(TPB2, 1)
void rnn_persistent(const float* __restrict__ W, float* out) {
    extern __shared__ float sm[];
    float* Wp = sm;                  // 4096 float2 (32KB): paired W, interleaved
    float* Ps = sm + 8 * 1024;       // partials: [32 ks][512 outputs + 4 pad]
    const int PSTR = 516;

    const int tid   = threadIdx.x;
    const int cbase = blockIdx.x * CPC;
    const int ks    = tid & 31;      // lane = k-split index
    const int wtile = tid >> 5;      // warp id 0..15 -> batch rows wtile*4..+3

    // Pack W slice into paired-interleaved layout:
    //   pair p holds cols (2p, 2p+1); element for k lives at
    //   float2 index ((j*8 + p*2 + (kq>>1))*32 + ks_k)*2 + (kq&1)
    //   with j=k>>7, ks_k=(k>>2)&31, kq=k&3.
    for (int i = tid; i < 4 * 1024; i += TPB2) {
        int p = i >> 10, k = i & 1023;
        float w0 = W[(size_t)k * HID + cbase + 2 * p];
        float w1 = W[(size_t)k * HID + cbase + 2 * p + 1];
        int j = k >> 7, ksk = (k >> 2) & 31, kq = k & 3;
        int idx = ((j * 8 + p * 2 + (kq >> 1)) * 32 + ksk) * 2 + (kq & 1);
        ((float2*)Wp)[idx] = make_float2(w0, w1);
    }

    __shared__ unsigned s_base;
    if (tid == 0) {
        unsigned p;
        asm volatile("ld.acquire.gpu.u32 %0, [%1];" : "=r"(p) : "l"(&g_phase) : "memory");
        s_base = p;
    }
    __syncthreads();
    const unsigned base = s_base;

    // Each thread finalizes ONE output o = tid  (o = b*8 + c)
    const int ob = tid >> 3;
    const size_t xv_off = (size_t)ob * HID + cbase + (tid & 7);
    float xv = g_xv[xv_off];

    const size_t hrow0 = (size_t)wtile * 4 * HID + (size_t)ks * 4;

    for (int t = 0; t < S_LEN; t++) {
#if HAS_F32X2
        ull acc2[4][4];
        #pragma unroll
        for (int b = 0; b < 4; b++)
            #pragma unroll
            for (int p = 0; p < 4; p++) acc2[b][p] = 0ULL;

        if (t > 0) {
            const float* prev = out + (size_t)(t - 1) * BH + hrow0;

            float4 h4[4];
            #pragma unroll
            for (int b = 0; b < 4; b++)
                h4[b] = __ldcg((const float4*)(prev + (size_t)b * HID));

            #pragma unroll 1
            for (int j = 0; j < 8; j++) {
                float4 hn[4];
                if (j < 7) {
                    #pragma unroll
                    for (int b = 0; b < 4; b++)
                        hn[b] = __ldcg((const float4*)(prev + (size_t)b * HID + j * 128 + 128));
                }

                // 8 dense conflict-free LDS.128 -> 16 b64 W-pair operands
                ulonglong2 wv[8];
                const ulonglong2* wj = (const ulonglong2*)Wp + (size_t)(j * 8) * 32 + ks;
                #pragma unroll
                for (int i = 0; i < 8; i++)
                    wv[i] = wj[(size_t)i * 32];

                #pragma unroll
                for (int kk = 0; kk < 4; kk++) {
                    const int ih = kk >> 1;      // khalf
                    ull w0 = (kk & 1) ? wv[0 + ih].y : wv[0 + ih].x;
                    ull w1 = (kk & 1) ? wv[2 + ih].y : wv[2 + ih].x;
                    ull w2 = (kk & 1) ? wv[4 + ih].y : wv[4 + ih].x;
                    ull w3 = (kk & 1) ? wv[6 + ih].y : wv[6 + ih].x;
                    #pragma unroll
                    for (int b = 0; b < 4; b++) {
                        float hk = ((const float*)&h4[b])[kk];
                        ull hd = pack2(hk, hk);
                        acc2[b][0] = ffma2(hd, w0, acc2[b][0]);
                        acc2[b][1] = ffma2(hd, w1, acc2[b][1]);
                        acc2[b][2] = ffma2(hd, w2, acc2[b][2]);
                        acc2[b][3] = ffma2(hd, w3, acc2[b][3]);
                    }
                }

                if (j < 7) {
                    #pragma unroll
                    for (int b = 0; b < 4; b++) h4[b] = hn[b];
                }
            }
        }

        // ---- k-split reduction (memory image identical to R12) ----
        float* prow = Ps + ks * PSTR + wtile * 32;
        #pragma unroll
        for (int b = 0; b < 4; b++) {
            *(ulonglong2*)(prow + b * 8)     = make_ulonglong2(acc2[b][0], acc2[b][1]);
            *(ulonglong2*)(prow + b * 8 + 4) = make_ulonglong2(acc2[b][2], acc2[b][3]);
        }
#else
        float acc[4][8];
        #pragma unroll
        for (int b = 0; b < 4; b++)
            #pragma unroll
            for (int c = 0; c < 8; c++) acc[b][c] = 0.f;

        if (t > 0) {
            const float* prev = out + (size_t)(t - 1) * BH + hrow0;
            float4 h4[4];
            #pragma unroll
            for (int b = 0; b < 4; b++)
                h4[b] = __ldcg((const float4*)(prev + (size_t)b * HID));

            #pragma unroll 1
            for (int j = 0; j < 8; j++) {
                float4 hn[4];
                if (j < 7) {
                    #pragma unroll
                    for (int b = 0; b < 4; b++)
                        hn[b] = __ldcg((const float4*)(prev + (size_t)b * HID + j * 128 + 128));
                }
                float4 wq[8];
                const float4* wj = (const float4*)Wp + (size_t)(j * 8) * 32 + ks;
                #pragma unroll
                for (int i = 0; i < 8; i++)
                    wq[i] = wj[(size_t)i * 32];

                #pragma unroll
                for (int kk = 0; kk < 4; kk++) {
                    const int ih = kk >> 1;
                    #pragma unroll
                    for (int b = 0; b < 4; b++) {
                        float hk = ((const float*)&h4[b])[kk];
                        #pragma unroll
                        for (int p = 0; p < 4; p++) {
                            const float4& v = wq[p * 2 + ih];
                            float wx = (kk & 1) ? v.z : v.x;
                            float wy = (kk & 1) ? v.w : v.y;
                            acc[b][2 * p]     = fmaf(hk, wx, acc[b][2 * p]);
                            acc[b][2 * p + 1] = fmaf(hk, wy, acc[b][2 * p + 1]);
                        }
                    }
                }
                if (j < 7) {
                    #pragma unroll
                    for (int b = 0; b < 4; b++) h4[b] = hn[b];
                }
            }
        }
        float* prow = Ps + ks * PSTR + wtile * 32;
        #pragma unroll
        for (int b = 0; b < 4; b++) {
            *(float4*)(prow + b * 8)     = make_float4(acc[b][0], acc[b][1],
                                                       acc[b][2], acc[b][3]);
            *(float4*)(prow + b * 8 + 4) = make_float4(acc[b][4], acc[b][5],
                                                       acc[b][6], acc[b][7]);
        }
#endif
        __syncthreads();

        float s = 0.f;
        #pragma unroll
        for (int p = 0; p < 32; p++)
            s += Ps[p * PSTR + tid];
        float r = tanhf(s + xv);

        out[(size_t)t * BH + xv_off] = r;
        if (t == S_LEN - 1)
            out[(size_t)S_LEN * BH + xv_off] = r;

        // ---- split grid barrier: arrive, prefetch next xv, wait ----
        __syncthreads();                  // stores issued + Ps reads done
        if (tid == 0) grid_arrive();
        if (t + 1 < S_LEN)
            xv = g_xv[(size_t)(t + 1) * BH + xv_off];
        if (tid == 0) grid_wait(base + (unsigned)t + 1u);
        __syncthreads();
    }
}

// =============================================================================
// launch
// =============================================================================
extern "C" void kernel_launch(void* const* d_in, const int* in_sizes, int n_in,
                              void* d_out, int out_size) {
    const float* x  = (const float*)d_in[0];
    const float* V  = (const float*)d_in[1];
    const float* W  = (const float*)d_in[2];
    const float* b  = (const float*)d_in[3];
    const float* b2 = (const float*)d_in[4];
    float* out = (float*)d_out;

    dim3 g1(HID / 128, (S_LEN * BATCH) / 128);
    xv_gemm<<<g1, 256>>>(x, V, b, b2);

    const int smem_bytes = (8 * 1024 + 32 * 516) * (int)sizeof(float); // 98816
    cudaFuncSetAttribute(rnn_persistent,
                         cudaFuncAttributeMaxDynamicSharedMemorySize, smem_bytes);
    rnn_persistent<<<NCTA, TPB2, smem_bytes>>>(W, out);
}